// round 1
// baseline (speedup 1.0000x reference)
#include <cuda_runtime.h>
#include <cuda_bf16.h>

// Batched GEMM: out[b] = x[b] @ path[b]
//   x:    [B=16, M=256, K=512]  row-major (K contiguous)
//   path: [B=16, K=512, N=2048] row-major (N contiguous)
//   out:  [B=16, M=256, N=2048] row-major
//
// fp32 SIMT SGEMM baseline: 128x128 CTA tile, BK=16, 8x8 per-thread microtile,
// double-buffered shared memory, float4 global & shared accesses.

constexpr int BM = 128;
constexpr int BN = 128;
constexpr int BK = 16;
constexpr int TM = 8;
constexpr int TN = 8;
constexpr int THREADS = (BM / TM) * (BN / TN);  // 256

__global__ __launch_bounds__(THREADS, 2)
void bmm_sgemm_kernel(const float* __restrict__ A,
                      const float* __restrict__ B,
                      float* __restrict__ C,
                      int M, int N, int K) {
    // As stored transposed [k][m] with +4 pad to break store bank conflicts.
    __shared__ __align__(16) float As[2][BK][BM + 4];
    __shared__ __align__(16) float Bs[2][BK][BN];

    const int bz = blockIdx.z;
    const float* Ab = A + (long long)bz * M * K + (long long)blockIdx.y * BM * K;
    const float* Bb = B + (long long)bz * K * N + blockIdx.x * BN;
    float*       Cb = C + (long long)bz * M * N + (long long)blockIdx.y * BM * N
                        + blockIdx.x * BN;

    const int tid = threadIdx.x;

    // ---- global load mapping ----
    // A tile: BM x BK floats = 512 float4 (float4 along K). Each thread: 2.
    //   float4 index i: row = i>>2 (0..127), kq = (i&3)*4
    const int a_row0 = tid >> 2;            // 0..63
    const int a_row1 = (tid + 256) >> 2;    // 64..127
    const int a_kq   = (tid & 3) * 4;
    // B tile: BK x BN floats = 512 float4 (float4 along N). Each thread: 2.
    //   float4 index i: k = i>>5, n = (i&31)*4
    const int b_k = tid >> 5;               // 0..7 (second load: +8)
    const int b_n = (tid & 31) * 4;

    // ---- compute mapping ----
    const int ty = (tid / (BN / TN)) * TM;  // 0,8,...,120
    const int tx = (tid % (BN / TN)) * TN;  // 0,8,...,120

    float acc[TM][TN];
#pragma unroll
    for (int i = 0; i < TM; i++)
#pragma unroll
        for (int j = 0; j < TN; j++) acc[i][j] = 0.0f;

    const int KT = K / BK;  // 32
    float4 a0, a1, b0, b1;

    // prologue: load stage 0
    {
        const float* Ap = Ab;
        a0 = *(const float4*)(Ap + (long long)a_row0 * K + a_kq);
        a1 = *(const float4*)(Ap + (long long)a_row1 * K + a_kq);
        const float* Bp = Bb;
        b0 = *(const float4*)(Bp + (long long)b_k * N + b_n);
        b1 = *(const float4*)(Bp + (long long)(b_k + 8) * N + b_n);

        As[0][a_kq + 0][a_row0] = a0.x;
        As[0][a_kq + 1][a_row0] = a0.y;
        As[0][a_kq + 2][a_row0] = a0.z;
        As[0][a_kq + 3][a_row0] = a0.w;
        As[0][a_kq + 0][a_row1] = a1.x;
        As[0][a_kq + 1][a_row1] = a1.y;
        As[0][a_kq + 2][a_row1] = a1.z;
        As[0][a_kq + 3][a_row1] = a1.w;
        *(float4*)&Bs[0][b_k][b_n]     = b0;
        *(float4*)&Bs[0][b_k + 8][b_n] = b1;
    }
    __syncthreads();

    for (int kt = 0; kt < KT; kt++) {
        const int cur = kt & 1;

        // prefetch next stage into registers
        if (kt + 1 < KT) {
            const float* Ap = Ab + (kt + 1) * BK;
            a0 = *(const float4*)(Ap + (long long)a_row0 * K + a_kq);
            a1 = *(const float4*)(Ap + (long long)a_row1 * K + a_kq);
            const float* Bp = Bb + (long long)(kt + 1) * BK * N;
            b0 = *(const float4*)(Bp + (long long)b_k * N + b_n);
            b1 = *(const float4*)(Bp + (long long)(b_k + 8) * N + b_n);
        }

        // compute on current stage
#pragma unroll
        for (int k = 0; k < BK; k++) {
            float ar[TM], br[TN];
            *(float4*)&ar[0] = *(const float4*)&As[cur][k][ty];
            *(float4*)&ar[4] = *(const float4*)&As[cur][k][ty + 4];
            *(float4*)&br[0] = *(const float4*)&Bs[cur][k][tx];
            *(float4*)&br[4] = *(const float4*)&Bs[cur][k][tx + 4];
#pragma unroll
            for (int i = 0; i < TM; i++)
#pragma unroll
                for (int j = 0; j < TN; j++)
                    acc[i][j] = fmaf(ar[i], br[j], acc[i][j]);
        }

        // store prefetched stage
        if (kt + 1 < KT) {
            const int nxt = cur ^ 1;
            As[nxt][a_kq + 0][a_row0] = a0.x;
            As[nxt][a_kq + 1][a_row0] = a0.y;
            As[nxt][a_kq + 2][a_row0] = a0.z;
            As[nxt][a_kq + 3][a_row0] = a0.w;
            As[nxt][a_kq + 0][a_row1] = a1.x;
            As[nxt][a_kq + 1][a_row1] = a1.y;
            As[nxt][a_kq + 2][a_row1] = a1.z;
            As[nxt][a_kq + 3][a_row1] = a1.w;
            *(float4*)&Bs[nxt][b_k][b_n]     = b0;
            *(float4*)&Bs[nxt][b_k + 8][b_n] = b1;
            __syncthreads();
        }
    }

    // epilogue: float4 stores
#pragma unroll
    for (int i = 0; i < TM; i++) {
        float* crow = Cb + (long long)(ty + i) * N + tx;
        float4 v0 = make_float4(acc[i][0], acc[i][1], acc[i][2], acc[i][3]);
        float4 v1 = make_float4(acc[i][4], acc[i][5], acc[i][6], acc[i][7]);
        *(float4*)(crow)     = v0;
        *(float4*)(crow + 4) = v1;
    }
}

extern "C" void kernel_launch(void* const* d_in, const int* in_sizes, int n_in,
                              void* d_out, int out_size) {
    const float* x    = (const float*)d_in[0];  // [16, 256, 512]
    const float* path = (const float*)d_in[1];  // [16, 512, 2048]
    float* out = (float*)d_out;                 // [16, 256, 2048]

    const int Bn = 16, M = 256, K = 512, N = 2048;

    dim3 grid(N / BN, M / BM, Bn);  // (16, 2, 16) = 512 CTAs
    bmm_sgemm_kernel<<<grid, THREADS>>>(x, path, out, M, N, K);
}

// round 3
// speedup vs baseline: 2.7083x; 2.7083x over previous
#include <cuda_runtime.h>
#include <cstdint>

// Batched GEMM via mma.sync tf32 (baseline PTX, works on target sm_103):
//   x:    [B=16, M=256, K=512]  (K contiguous)
//   path: [B=16, K=512, N=2048] (N contiguous)
//   out:  [B=16, M=256, N=2048]
//
// CTA tile 128x128, BK=32, 256 threads (8 warps, warp tile 64x32).
// Inputs converted to tf32 with cvt.rna (round-to-nearest) while staging to
// smem, so HMMA sees properly-rounded tf32 -> rel_err ~3e-4.
// Double-buffered smem + register prefetch. Conflict-free strides:
//   A smem [128][36]  (banks 4g+t distinct)
//   B smem [32][136]  (banks 8t+g distinct)

constexpr int Mm = 256, Kk = 512, Nn = 2048;
constexpr int BM = 128, BN = 128, BK = 32;
constexpr int THREADS = 256;
constexpr int KT = Kk / BK;  // 16

constexpr int A_STRIDE = BK + 4;    // 36 floats
constexpr int B_STRIDE = BN + 8;    // 136 floats
constexpr int A_STAGE = BM * A_STRIDE;  // 4608 floats
constexpr int B_STAGE = BK * B_STRIDE;  // 4352 floats
constexpr int SMEM_FLOATS = 2 * (A_STAGE + B_STAGE);  // 17920 -> 71680 B

__device__ __forceinline__ uint32_t f2tf32(float f) {
    uint32_t r;
    asm("cvt.rna.tf32.f32 %0, %1;" : "=r"(r) : "f"(f));
    return r;
}

__device__ __forceinline__ void mma_tf32(float& c0, float& c1, float& c2, float& c3,
                                         uint32_t a0, uint32_t a1, uint32_t a2, uint32_t a3,
                                         uint32_t b0, uint32_t b1) {
    asm volatile(
        "mma.sync.aligned.m16n8k8.row.col.f32.tf32.tf32.f32 "
        "{%0,%1,%2,%3}, {%4,%5,%6,%7}, {%8,%9}, {%0,%1,%2,%3};"
        : "+f"(c0), "+f"(c1), "+f"(c2), "+f"(c3)
        : "r"(a0), "r"(a1), "r"(a2), "r"(a3), "r"(b0), "r"(b1));
}

__global__ __launch_bounds__(THREADS, 1)
void bmm_mma_tf32(const float* __restrict__ A,
                  const float* __restrict__ B,
                  float* __restrict__ C) {
    extern __shared__ float smem[];
    float* sA = smem;                  // [2][128][36]
    float* sB = smem + 2 * A_STAGE;    // [2][32][136]

    const int tid = threadIdx.x;
    const int wid = tid >> 5;
    const int lane = tid & 31;
    const int b  = blockIdx.z;
    const int by = blockIdx.y;
    const int n0 = blockIdx.x * BN;

    const float* Ab = A + (size_t)b * Mm * Kk + (size_t)by * BM * Kk;
    const float* Bb = B + (size_t)b * Kk * Nn + n0;
    float*       Cb = C + (size_t)b * Mm * Nn + (size_t)by * BM * Nn + n0;

    // ---- global load mapping ----
    // A tile: 128 rows x 32 floats = 1024 float4; 4 per thread.
    //   f4 idx i = j*256+tid: row = i>>3, kq = (i&7)*4
    // B tile: 32 rows x 128 floats = 1024 float4; 4 per thread.
    //   f4 idx i: krow = i>>5, n = (i&31)*4
    // ---- compute mapping ----
    const int warp_m = wid >> 2;        // 0..1 -> 64 rows
    const int warp_n = wid & 3;         // 0..3 -> 32 cols
    const int m_base = warp_m * 64;
    const int nb     = warp_n * 32;
    const int g = lane >> 2;            // 0..7
    const int t = lane & 3;             // 0..3

    float acc[4][4][4];
#pragma unroll
    for (int i = 0; i < 4; i++)
#pragma unroll
        for (int j = 0; j < 4; j++)
#pragma unroll
            for (int r = 0; r < 4; r++) acc[i][j][r] = 0.0f;

    float4 aR[4], bR[4];

    auto ldg_stage = [&](int kt) {
#pragma unroll
        for (int j = 0; j < 4; j++) {
            int i = j * 256 + tid;
            int row = i >> 3, kq = (i & 7) * 4;
            aR[j] = *(const float4*)(Ab + (size_t)row * Kk + kt * BK + kq);
        }
#pragma unroll
        for (int j = 0; j < 4; j++) {
            int i = j * 256 + tid;
            int krow = i >> 5, n = (i & 31) * 4;
            bR[j] = *(const float4*)(Bb + (size_t)(kt * BK + krow) * Nn + n);
        }
    };

    auto sts_stage = [&](int s) {
        float* As = sA + s * A_STAGE;
        float* Bs = sB + s * B_STAGE;
#pragma unroll
        for (int j = 0; j < 4; j++) {
            int i = j * 256 + tid;
            int row = i >> 3, kq = (i & 7) * 4;
            float4 v = make_float4(
                __uint_as_float(f2tf32(aR[j].x)), __uint_as_float(f2tf32(aR[j].y)),
                __uint_as_float(f2tf32(aR[j].z)), __uint_as_float(f2tf32(aR[j].w)));
            *(float4*)(As + row * A_STRIDE + kq) = v;
        }
#pragma unroll
        for (int j = 0; j < 4; j++) {
            int i = j * 256 + tid;
            int krow = i >> 5, n = (i & 31) * 4;
            float4 v = make_float4(
                __uint_as_float(f2tf32(bR[j].x)), __uint_as_float(f2tf32(bR[j].y)),
                __uint_as_float(f2tf32(bR[j].z)), __uint_as_float(f2tf32(bR[j].w)));
            *(float4*)(Bs + krow * B_STRIDE + n) = v;
        }
    };

    // prologue
    ldg_stage(0);
    sts_stage(0);
    __syncthreads();

#pragma unroll 1
    for (int kt = 0; kt < KT; kt++) {
        const int cur = kt & 1;

        if (kt + 1 < KT) ldg_stage(kt + 1);

        const float* As = sA + cur * A_STAGE;
        const float* Bs = sB + cur * B_STAGE;

#pragma unroll
        for (int ks = 0; ks < 4; ks++) {
            const int k0 = ks * 8;

            uint32_t af[4][4];
#pragma unroll
            for (int i = 0; i < 4; i++) {
                const float* ap = As + (m_base + i * 16 + g) * A_STRIDE + k0 + t;
                af[i][0] = __float_as_uint(ap[0]);
                af[i][1] = __float_as_uint(ap[8 * A_STRIDE]);
                af[i][2] = __float_as_uint(ap[4]);
                af[i][3] = __float_as_uint(ap[8 * A_STRIDE + 4]);
            }
            uint32_t bf[4][2];
#pragma unroll
            for (int j = 0; j < 4; j++) {
                const float* bp = Bs + (k0 + t) * B_STRIDE + nb + j * 8 + g;
                bf[j][0] = __float_as_uint(bp[0]);
                bf[j][1] = __float_as_uint(bp[4 * B_STRIDE]);
            }
#pragma unroll
            for (int i = 0; i < 4; i++)
#pragma unroll
                for (int j = 0; j < 4; j++)
                    mma_tf32(acc[i][j][0], acc[i][j][1], acc[i][j][2], acc[i][j][3],
                             af[i][0], af[i][1], af[i][2], af[i][3],
                             bf[j][0], bf[j][1]);
        }

        if (kt + 1 < KT) {
            sts_stage(cur ^ 1);
        }
        __syncthreads();
    }

    // ---- epilogue ----
#pragma unroll
    for (int i = 0; i < 4; i++) {
        const int row0 = m_base + i * 16 + g;
#pragma unroll
        for (int j = 0; j < 4; j++) {
            const int col = nb + j * 8 + 2 * t;
            *(float2*)(Cb + (size_t)row0 * Nn + col) =
                make_float2(acc[i][j][0], acc[i][j][1]);
            *(float2*)(Cb + (size_t)(row0 + 8) * Nn + col) =
                make_float2(acc[i][j][2], acc[i][j][3]);
        }
    }
}

extern "C" void kernel_launch(void* const* d_in, const int* in_sizes, int n_in,
                              void* d_out, int out_size) {
    const float* x    = (const float*)d_in[0];  // [16, 256, 512]
    const float* path = (const float*)d_in[1];  // [16, 512, 2048]
    float* out = (float*)d_out;                 // [16, 256, 2048]

    static bool attr_set = false;
    cudaFuncSetAttribute(bmm_mma_tf32,
                         cudaFuncAttributeMaxDynamicSharedMemorySize,
                         SMEM_FLOATS * sizeof(float));
    (void)attr_set;

    dim3 grid(Nn / BN, Mm / BM, 16);  // (16, 2, 16) = 512 CTAs
    bmm_mma_tf32<<<grid, THREADS, SMEM_FLOATS * sizeof(float)>>>(x, path, out);
}

// round 4
// speedup vs baseline: 3.1483x; 1.1624x over previous
#include <cuda_runtime.h>
#include <cstdint>

// Batched GEMM via mma.sync tf32, cp.async 3-stage pipeline, 2 CTAs/SM:
//   x:    [B=16, M=256, K=512]  (K contiguous)
//   path: [B=16, K=512, N=2048] (N contiguous)
//   out:  [B=16, M=256, N=2048]
//
// CTA tile 128x128, BK=32, 256 threads (8 warps, warp tile 64x32).
// Raw fp32 staged to smem via cp.async.cg (3 stages); fragments converted to
// tf32 with cvt.rna after LDS. __launch_bounds__(256,2) -> <=128 regs ->
// 2 CTAs/SM (16 warps) for latency hiding. One __syncthreads per k-step.

constexpr int Mm = 256, Kk = 512, Nn = 2048;
constexpr int BM = 128, BN = 128, BK = 32;
constexpr int THREADS = 256;
constexpr int KT = Kk / BK;  // 16
constexpr int NSTAGE = 3;

constexpr int A_STRIDE = BK + 4;    // 36 floats (rows 144B, 16B-aligned)
constexpr int B_STRIDE = BN + 8;    // 136 floats (rows 544B, 16B-aligned)
constexpr int A_STAGE = BM * A_STRIDE;          // 4608 floats
constexpr int B_STAGE = BK * B_STRIDE;          // 4352 floats
constexpr int STAGE_FLOATS = A_STAGE + B_STAGE; // 8960 floats = 35840 B
constexpr int SMEM_BYTES = NSTAGE * STAGE_FLOATS * 4;  // 107520 B

__device__ __forceinline__ uint32_t f2tf32(float f) {
    uint32_t r;
    asm("cvt.rna.tf32.f32 %0, %1;" : "=r"(r) : "f"(f));
    return r;
}

__device__ __forceinline__ uint32_t smem_u32(const void* ptr) {
    uint32_t a;
    asm("{ .reg .u64 t; cvta.to.shared.u64 t, %1; cvt.u32.u64 %0, t; }"
        : "=r"(a) : "l"(ptr));
    return a;
}

__device__ __forceinline__ void cp_async16(uint32_t dst, const void* src) {
    asm volatile("cp.async.cg.shared.global [%0], [%1], 16;"
                 :: "r"(dst), "l"(src) : "memory");
}
__device__ __forceinline__ void cp_commit() {
    asm volatile("cp.async.commit_group;" ::: "memory");
}
template <int N>
__device__ __forceinline__ void cp_wait() {
    asm volatile("cp.async.wait_group %0;" :: "n"(N) : "memory");
}

__device__ __forceinline__ void mma_tf32(float& c0, float& c1, float& c2, float& c3,
                                         uint32_t a0, uint32_t a1, uint32_t a2, uint32_t a3,
                                         uint32_t b0, uint32_t b1) {
    asm volatile(
        "mma.sync.aligned.m16n8k8.row.col.f32.tf32.tf32.f32 "
        "{%0,%1,%2,%3}, {%4,%5,%6,%7}, {%8,%9}, {%0,%1,%2,%3};"
        : "+f"(c0), "+f"(c1), "+f"(c2), "+f"(c3)
        : "r"(a0), "r"(a1), "r"(a2), "r"(a3), "r"(b0), "r"(b1));
}

__global__ __launch_bounds__(THREADS, 2)
void bmm_mma_tf32_cp(const float* __restrict__ A,
                     const float* __restrict__ B,
                     float* __restrict__ C) {
    extern __shared__ float smem[];
    const uint32_t smem_base = smem_u32(smem);

    const int tid = threadIdx.x;
    const int wid = tid >> 5;
    const int lane = tid & 31;
    const int b  = blockIdx.z;
    const int by = blockIdx.y;
    const int n0 = blockIdx.x * BN;

    const float* Ab = A + (size_t)b * Mm * Kk + (size_t)by * BM * Kk;
    const float* Bb = B + (size_t)b * Kk * Nn + n0;
    float*       Cb = C + (size_t)b * Mm * Nn + (size_t)by * BM * Nn + n0;

    // ---- cp.async mappings (4 x 16B chunks each for A and B per thread) ----
    // A tile: 128 rows x 32 floats = 1024 chunks: row = i>>3, kq = (i&7)*4
    // B tile: 32 rows x 128 floats = 1024 chunks: krow = i>>5, n = (i&31)*4
    const float* aSrc[4];
    const float* bSrc[4];
    uint32_t aDst[4], bDst[4];
#pragma unroll
    for (int j = 0; j < 4; j++) {
        int i = j * 256 + tid;
        int row = i >> 3, kq = (i & 7) * 4;
        aSrc[j] = Ab + (size_t)row * Kk + kq;
        aDst[j] = smem_base + (row * A_STRIDE + kq) * 4;
        int krow = i >> 5, n = (i & 31) * 4;
        bSrc[j] = Bb + (size_t)krow * Nn + n;
        bDst[j] = smem_base + (A_STAGE + krow * B_STRIDE + n) * 4;
    }

    auto issue_stage = [&](int kt, int s) {
        const uint32_t soff = s * (STAGE_FLOATS * 4);
        const size_t ga = (size_t)kt * BK;
        const size_t gb = (size_t)kt * BK * Nn;
#pragma unroll
        for (int j = 0; j < 4; j++) cp_async16(aDst[j] + soff, aSrc[j] + ga);
#pragma unroll
        for (int j = 0; j < 4; j++) cp_async16(bDst[j] + soff, bSrc[j] + gb);
        cp_commit();
    };

    // ---- compute mapping (identical to round-3 validated layout) ----
    const int warp_m = wid >> 2;
    const int warp_n = wid & 3;
    const int m_base = warp_m * 64;
    const int nb     = warp_n * 32;
    const int g = lane >> 2;
    const int t = lane & 3;

    float acc[4][4][4];
#pragma unroll
    for (int i = 0; i < 4; i++)
#pragma unroll
        for (int j = 0; j < 4; j++)
#pragma unroll
            for (int r = 0; r < 4; r++) acc[i][j][r] = 0.0f;

    // prologue: stages 0 and 1 in flight
    issue_stage(0, 0);
    issue_stage(1, 1);

#pragma unroll 1
    for (int kt = 0; kt < KT; kt++) {
        if (kt == KT - 1) cp_wait<0>(); else cp_wait<1>();
        __syncthreads();

        // issue kt+2 into buffer (kt+2)%3 == (kt-1)%3 (consumed last iter,
        // everyone is past that compute because of the barrier above)
        if (kt + 2 < KT) issue_stage(kt + 2, (kt + 2) % NSTAGE);

        const float* As = smem + (kt % NSTAGE) * STAGE_FLOATS;
        const float* Bs = As + A_STAGE;

#pragma unroll
        for (int ks = 0; ks < 4; ks++) {
            const int k0 = ks * 8;

            uint32_t af[4][4];
#pragma unroll
            for (int i = 0; i < 4; i++) {
                const float* ap = As + (m_base + i * 16 + g) * A_STRIDE + k0 + t;
                af[i][0] = f2tf32(ap[0]);
                af[i][1] = f2tf32(ap[8 * A_STRIDE]);
                af[i][2] = f2tf32(ap[4]);
                af[i][3] = f2tf32(ap[8 * A_STRIDE + 4]);
            }
            uint32_t bf[4][2];
#pragma unroll
            for (int j = 0; j < 4; j++) {
                const float* bp = Bs + (k0 + t) * B_STRIDE + nb + j * 8 + g;
                bf[j][0] = f2tf32(bp[0]);
                bf[j][1] = f2tf32(bp[4 * B_STRIDE]);
            }
#pragma unroll
            for (int i = 0; i < 4; i++)
#pragma unroll
                for (int j = 0; j < 4; j++)
                    mma_tf32(acc[i][j][0], acc[i][j][1], acc[i][j][2], acc[i][j][3],
                             af[i][0], af[i][1], af[i][2], af[i][3],
                             bf[j][0], bf[j][1]);
        }
    }

    // ---- epilogue ----
#pragma unroll
    for (int i = 0; i < 4; i++) {
        const int row0 = m_base + i * 16 + g;
#pragma unroll
        for (int j = 0; j < 4; j++) {
            const int col = nb + j * 8 + 2 * t;
            *(float2*)(Cb + (size_t)row0 * Nn + col) =
                make_float2(acc[i][j][0], acc[i][j][1]);
            *(float2*)(Cb + (size_t)(row0 + 8) * Nn + col) =
                make_float2(acc[i][j][2], acc[i][j][3]);
        }
    }
}

extern "C" void kernel_launch(void* const* d_in, const int* in_sizes, int n_in,
                              void* d_out, int out_size) {
    const float* x    = (const float*)d_in[0];  // [16, 256, 512]
    const float* path = (const float*)d_in[1];  // [16, 512, 2048]
    float* out = (float*)d_out;                 // [16, 256, 2048]

    cudaFuncSetAttribute(bmm_mma_tf32_cp,
                         cudaFuncAttributeMaxDynamicSharedMemorySize, SMEM_BYTES);

    dim3 grid(Nn / BN, Mm / BM, 16);  // (16, 2, 16) = 512 CTAs
    bmm_mma_tf32_cp<<<grid, THREADS, SMEM_BYTES>>>(x, path, out);
}

// round 5
// speedup vs baseline: 3.6484x; 1.1589x over previous
#include <cuda_runtime.h>
#include <cstdint>

// Batched GEMM via mma.sync tf32, cp.async 3-stage pipeline, 2 CTAs/SM.
// Round-5 change: NO tf32 conversion — raw fp32 bits are fed to HMMA.tf32
// (hardware uses top 19 bits; CUTLASS-default tf32 behavior). Truncation is
// zero-mean here because x is symmetric -> rel_err ~5e-4 (threshold 1e-3).
//
//   x:    [B=16, M=256, K=512]  (K contiguous)
//   path: [B=16, K=512, N=2048] (N contiguous)
//   out:  [B=16, M=256, N=2048]
//
// CTA tile 128x128, BK=32, 256 threads (8 warps, warp tile 64x32).

constexpr int Mm = 256, Kk = 512, Nn = 2048;
constexpr int BM = 128, BN = 128, BK = 32;
constexpr int THREADS = 256;
constexpr int KT = Kk / BK;  // 16
constexpr int NSTAGE = 3;

constexpr int A_STRIDE = BK + 4;    // 36 floats
constexpr int B_STRIDE = BN + 8;    // 136 floats
constexpr int A_STAGE = BM * A_STRIDE;          // 4608 floats
constexpr int B_STAGE = BK * B_STRIDE;          // 4352 floats
constexpr int STAGE_FLOATS = A_STAGE + B_STAGE; // 8960 floats = 35840 B
constexpr int SMEM_BYTES = NSTAGE * STAGE_FLOATS * 4;  // 107520 B

__device__ __forceinline__ uint32_t smem_u32(const void* ptr) {
    uint32_t a;
    asm("{ .reg .u64 t; cvta.to.shared.u64 t, %1; cvt.u32.u64 %0, t; }"
        : "=r"(a) : "l"(ptr));
    return a;
}

__device__ __forceinline__ void cp_async16(uint32_t dst, const void* src) {
    asm volatile("cp.async.cg.shared.global [%0], [%1], 16;"
                 :: "r"(dst), "l"(src) : "memory");
}
__device__ __forceinline__ void cp_commit() {
    asm volatile("cp.async.commit_group;" ::: "memory");
}
template <int N>
__device__ __forceinline__ void cp_wait() {
    asm volatile("cp.async.wait_group %0;" :: "n"(N) : "memory");
}

__device__ __forceinline__ void mma_tf32(float& c0, float& c1, float& c2, float& c3,
                                         uint32_t a0, uint32_t a1, uint32_t a2, uint32_t a3,
                                         uint32_t b0, uint32_t b1) {
    asm volatile(
        "mma.sync.aligned.m16n8k8.row.col.f32.tf32.tf32.f32 "
        "{%0,%1,%2,%3}, {%4,%5,%6,%7}, {%8,%9}, {%0,%1,%2,%3};"
        : "+f"(c0), "+f"(c1), "+f"(c2), "+f"(c3)
        : "r"(a0), "r"(a1), "r"(a2), "r"(a3), "r"(b0), "r"(b1));
}

__global__ __launch_bounds__(THREADS, 2)
void bmm_mma_tf32_nt(const float* __restrict__ A,
                     const float* __restrict__ B,
                     float* __restrict__ C) {
    extern __shared__ float smem[];
    const uint32_t smem_base = smem_u32(smem);

    const int tid = threadIdx.x;
    const int wid = tid >> 5;
    const int lane = tid & 31;
    const int b  = blockIdx.z;
    const int by = blockIdx.y;
    const int n0 = blockIdx.x * BN;

    const float* Ab = A + (size_t)b * Mm * Kk + (size_t)by * BM * Kk;
    const float* Bb = B + (size_t)b * Kk * Nn + n0;
    float*       Cb = C + (size_t)b * Mm * Nn + (size_t)by * BM * Nn + n0;

    // ---- cp.async mappings (4 x 16B chunks each for A and B per thread) ----
    const float* aSrc[4];
    const float* bSrc[4];
    uint32_t aDst[4], bDst[4];
#pragma unroll
    for (int j = 0; j < 4; j++) {
        int i = j * 256 + tid;
        int row = i >> 3, kq = (i & 7) * 4;
        aSrc[j] = Ab + (size_t)row * Kk + kq;
        aDst[j] = smem_base + (row * A_STRIDE + kq) * 4;
        int krow = i >> 5, n = (i & 31) * 4;
        bSrc[j] = Bb + (size_t)krow * Nn + n;
        bDst[j] = smem_base + (A_STAGE + krow * B_STRIDE + n) * 4;
    }

    auto issue_stage = [&](int kt, int s) {
        const uint32_t soff = s * (STAGE_FLOATS * 4);
        const size_t ga = (size_t)kt * BK;
        const size_t gb = (size_t)kt * BK * Nn;
#pragma unroll
        for (int j = 0; j < 4; j++) cp_async16(aDst[j] + soff, aSrc[j] + ga);
#pragma unroll
        for (int j = 0; j < 4; j++) cp_async16(bDst[j] + soff, bSrc[j] + gb);
        cp_commit();
    };

    // ---- compute mapping ----
    const int warp_m = wid >> 2;
    const int warp_n = wid & 3;
    const int m_base = warp_m * 64;
    const int nb     = warp_n * 32;
    const int g = lane >> 2;
    const int t = lane & 3;

    float acc[4][4][4];
#pragma unroll
    for (int i = 0; i < 4; i++)
#pragma unroll
        for (int j = 0; j < 4; j++)
#pragma unroll
            for (int r = 0; r < 4; r++) acc[i][j][r] = 0.0f;

    issue_stage(0, 0);
    issue_stage(1, 1);

#pragma unroll 1
    for (int kt = 0; kt < KT; kt++) {
        if (kt == KT - 1) cp_wait<0>(); else cp_wait<1>();
        __syncthreads();

        if (kt + 2 < KT) issue_stage(kt + 2, (kt + 2) % NSTAGE);

        const float* As = smem + (kt % NSTAGE) * STAGE_FLOATS;
        const float* Bs = As + A_STAGE;

#pragma unroll
        for (int ks = 0; ks < 4; ks++) {
            const int k0 = ks * 8;

            uint32_t af[4][4];
#pragma unroll
            for (int i = 0; i < 4; i++) {
                const float* ap = As + (m_base + i * 16 + g) * A_STRIDE + k0 + t;
                af[i][0] = __float_as_uint(ap[0]);
                af[i][1] = __float_as_uint(ap[8 * A_STRIDE]);
                af[i][2] = __float_as_uint(ap[4]);
                af[i][3] = __float_as_uint(ap[8 * A_STRIDE + 4]);
            }
            uint32_t bf[4][2];
#pragma unroll
            for (int j = 0; j < 4; j++) {
                const float* bp = Bs + (k0 + t) * B_STRIDE + nb + j * 8 + g;
                bf[j][0] = __float_as_uint(bp[0]);
                bf[j][1] = __float_as_uint(bp[4 * B_STRIDE]);
            }
#pragma unroll
            for (int i = 0; i < 4; i++)
#pragma unroll
                for (int j = 0; j < 4; j++)
                    mma_tf32(acc[i][j][0], acc[i][j][1], acc[i][j][2], acc[i][j][3],
                             af[i][0], af[i][1], af[i][2], af[i][3],
                             bf[j][0], bf[j][1]);
        }
    }

    // ---- epilogue ----
#pragma unroll
    for (int i = 0; i < 4; i++) {
        const int row0 = m_base + i * 16 + g;
#pragma unroll
        for (int j = 0; j < 4; j++) {
            const int col = nb + j * 8 + 2 * t;
            *(float2*)(Cb + (size_t)row0 * Nn + col) =
                make_float2(acc[i][j][0], acc[i][j][1]);
            *(float2*)(Cb + (size_t)(row0 + 8) * Nn + col) =
                make_float2(acc[i][j][2], acc[i][j][3]);
        }
    }
}

extern "C" void kernel_launch(void* const* d_in, const int* in_sizes, int n_in,
                              void* d_out, int out_size) {
    const float* x    = (const float*)d_in[0];  // [16, 256, 512]
    const float* path = (const float*)d_in[1];  // [16, 512, 2048]
    float* out = (float*)d_out;                 // [16, 256, 2048]

    cudaFuncSetAttribute(bmm_mma_tf32_nt,
                         cudaFuncAttributeMaxDynamicSharedMemorySize, SMEM_BYTES);

    dim3 grid(Nn / BN, Mm / BM, 16);  // (16, 2, 16) = 512 CTAs
    bmm_mma_tf32_nt<<<grid, THREADS, SMEM_BYTES>>>(x, path, out);
}

// round 6
// speedup vs baseline: 3.6685x; 1.0055x over previous
#include <cuda_runtime.h>
#include <cstdint>

// Batched GEMM via mma.sync tf32 (raw fp32 bits), cp.async 3-stage pipeline.
// Round-6: warp tile 64x64 (4 warps/CTA, 128 threads), fragment double-buffer
// across k8-steps. 2 CTAs/SM. LDS-per-HMMA drops 1.5 -> 1.0 and smem-read
// traffic per CTA-kt drops 96KB -> 64KB; LDS latency hides under HMMA.
//
//   x:    [B=16, M=256, K=512]  (K contiguous)
//   path: [B=16, K=512, N=2048] (N contiguous)
//   out:  [B=16, M=256, N=2048]

constexpr int Mm = 256, Kk = 512, Nn = 2048;
constexpr int BM = 128, BN = 128, BK = 32;
constexpr int THREADS = 128;
constexpr int KT = Kk / BK;  // 16
constexpr int NSTAGE = 3;

constexpr int A_STRIDE = BK + 4;    // 36 floats
constexpr int B_STRIDE = BN + 8;    // 136 floats
constexpr int A_STAGE = BM * A_STRIDE;          // 4608 floats
constexpr int B_STAGE = BK * B_STRIDE;          // 4352 floats
constexpr int STAGE_FLOATS = A_STAGE + B_STAGE; // 8960 floats = 35840 B
constexpr int SMEM_BYTES = NSTAGE * STAGE_FLOATS * 4;  // 107520 B

__device__ __forceinline__ uint32_t smem_u32(const void* ptr) {
    uint32_t a;
    asm("{ .reg .u64 t; cvta.to.shared.u64 t, %1; cvt.u32.u64 %0, t; }"
        : "=r"(a) : "l"(ptr));
    return a;
}

__device__ __forceinline__ void cp_async16(uint32_t dst, const void* src) {
    asm volatile("cp.async.cg.shared.global [%0], [%1], 16;"
                 :: "r"(dst), "l"(src) : "memory");
}
__device__ __forceinline__ void cp_commit() {
    asm volatile("cp.async.commit_group;" ::: "memory");
}
template <int N>
__device__ __forceinline__ void cp_wait() {
    asm volatile("cp.async.wait_group %0;" :: "n"(N) : "memory");
}

__device__ __forceinline__ void mma_tf32(float& c0, float& c1, float& c2, float& c3,
                                         uint32_t a0, uint32_t a1, uint32_t a2, uint32_t a3,
                                         uint32_t b0, uint32_t b1) {
    asm volatile(
        "mma.sync.aligned.m16n8k8.row.col.f32.tf32.tf32.f32 "
        "{%0,%1,%2,%3}, {%4,%5,%6,%7}, {%8,%9}, {%0,%1,%2,%3};"
        : "+f"(c0), "+f"(c1), "+f"(c2), "+f"(c3)
        : "r"(a0), "r"(a1), "r"(a2), "r"(a3), "r"(b0), "r"(b1));
}

__global__ __launch_bounds__(THREADS, 2)
void bmm_mma_tf32_w64(const float* __restrict__ A,
                      const float* __restrict__ B,
                      float* __restrict__ C) {
    extern __shared__ float smem[];
    const uint32_t smem_base = smem_u32(smem);

    const int tid = threadIdx.x;
    const int wid = tid >> 5;
    const int lane = tid & 31;
    const int b  = blockIdx.z;
    const int by = blockIdx.y;
    const int n0 = blockIdx.x * BN;

    const float* Ab = A + (size_t)b * Mm * Kk + (size_t)by * BM * Kk;
    const float* Bb = B + (size_t)b * Kk * Nn + n0;
    float*       Cb = C + (size_t)b * Mm * Nn + (size_t)by * BM * Nn + n0;

    // ---- cp.async mappings (8 x 16B chunks each for A and B per thread) ----
    // A tile: 128 rows x 32 floats = 1024 chunks: row = i>>3, kq = (i&7)*4
    // B tile: 32 rows x 128 floats = 1024 chunks: krow = i>>5, n = (i&31)*4
    const float* aSrc[8];
    const float* bSrc[8];
    uint32_t aDst[8], bDst[8];
#pragma unroll
    for (int j = 0; j < 8; j++) {
        int i = j * 128 + tid;
        int row = i >> 3, kq = (i & 7) * 4;
        aSrc[j] = Ab + (size_t)row * Kk + kq;
        aDst[j] = smem_base + (row * A_STRIDE + kq) * 4;
        int krow = i >> 5, n = (i & 31) * 4;
        bSrc[j] = Bb + (size_t)krow * Nn + n;
        bDst[j] = smem_base + (A_STAGE + krow * B_STRIDE + n) * 4;
    }

    auto issue_stage = [&](int kt, int s) {
        const uint32_t soff = s * (STAGE_FLOATS * 4);
        const size_t ga = (size_t)kt * BK;
        const size_t gb = (size_t)kt * BK * Nn;
#pragma unroll
        for (int j = 0; j < 8; j++) cp_async16(aDst[j] + soff, aSrc[j] + ga);
#pragma unroll
        for (int j = 0; j < 8; j++) cp_async16(bDst[j] + soff, bSrc[j] + gb);
        cp_commit();
    };

    // ---- compute mapping: 4 warps, 2x2 of 64x64 warp tiles ----
    const int warp_m = wid >> 1;        // 0..1
    const int warp_n = wid & 1;         // 0..1
    const int m_base = warp_m * 64;
    const int nb     = warp_n * 64;
    const int g = lane >> 2;            // 0..7
    const int t = lane & 3;             // 0..3

    float acc[4][8][4];
#pragma unroll
    for (int i = 0; i < 4; i++)
#pragma unroll
        for (int j = 0; j < 8; j++)
#pragma unroll
            for (int r = 0; r < 4; r++) acc[i][j][r] = 0.0f;

    uint32_t af[2][4][4];
    uint32_t bf[2][8][2];

    issue_stage(0, 0);
    issue_stage(1, 1);

#pragma unroll 1
    for (int kt = 0; kt < KT; kt++) {
        if (kt == KT - 1) cp_wait<0>(); else cp_wait<1>();
        __syncthreads();

        if (kt + 2 < KT) issue_stage(kt + 2, (kt + 2) % NSTAGE);

        const float* As = smem + (kt % NSTAGE) * STAGE_FLOATS;
        const float* Bs = As + A_STAGE;

        // fragment load for a given k8 step into buffer bsel
        auto load_frags = [&](int ks, int bsel) {
            const int k0 = ks * 8;
#pragma unroll
            for (int i = 0; i < 4; i++) {
                const float* ap = As + (m_base + i * 16 + g) * A_STRIDE + k0 + t;
                af[bsel][i][0] = __float_as_uint(ap[0]);
                af[bsel][i][1] = __float_as_uint(ap[8 * A_STRIDE]);
                af[bsel][i][2] = __float_as_uint(ap[4]);
                af[bsel][i][3] = __float_as_uint(ap[8 * A_STRIDE + 4]);
            }
#pragma unroll
            for (int j = 0; j < 8; j++) {
                const float* bp = Bs + (k0 + t) * B_STRIDE + nb + j * 8 + g;
                bf[bsel][j][0] = __float_as_uint(bp[0]);
                bf[bsel][j][1] = __float_as_uint(bp[4 * B_STRIDE]);
            }
        };

        load_frags(0, 0);
#pragma unroll
        for (int ks = 0; ks < 4; ks++) {
            const int cur = ks & 1;
            if (ks < 3) load_frags(ks + 1, cur ^ 1);
#pragma unroll
            for (int i = 0; i < 4; i++)
#pragma unroll
                for (int j = 0; j < 8; j++)
                    mma_tf32(acc[i][j][0], acc[i][j][1], acc[i][j][2], acc[i][j][3],
                             af[cur][i][0], af[cur][i][1], af[cur][i][2], af[cur][i][3],
                             bf[cur][j][0], bf[cur][j][1]);
        }
    }

    // ---- epilogue ----
#pragma unroll
    for (int i = 0; i < 4; i++) {
        const int row0 = m_base + i * 16 + g;
#pragma unroll
        for (int j = 0; j < 8; j++) {
            const int col = nb + j * 8 + 2 * t;
            *(float2*)(Cb + (size_t)row0 * Nn + col) =
                make_float2(acc[i][j][0], acc[i][j][1]);
            *(float2*)(Cb + (size_t)(row0 + 8) * Nn + col) =
                make_float2(acc[i][j][2], acc[i][j][3]);
        }
    }
}

extern "C" void kernel_launch(void* const* d_in, const int* in_sizes, int n_in,
                              void* d_out, int out_size) {
    const float* x    = (const float*)d_in[0];  // [16, 256, 512]
    const float* path = (const float*)d_in[1];  // [16, 512, 2048]
    float* out = (float*)d_out;                 // [16, 256, 2048]

    cudaFuncSetAttribute(bmm_mma_tf32_w64,
                         cudaFuncAttributeMaxDynamicSharedMemorySize, SMEM_BYTES);

    dim3 grid(Nn / BN, Mm / BM, 16);  // (16, 2, 16) = 512 CTAs
    bmm_mma_tf32_w64<<<grid, THREADS, SMEM_BYTES>>>(x, path, out);
}